// round 10
// baseline (speedup 1.0000x reference)
#include <cuda_runtime.h>
#include <cuda_fp16.h>
#include <stdint.h>

#define B_SZ   16384
#define N_NODE 12
#define C_DIM  512
#define M_ROWS (B_SZ * N_NODE)   // 196608

// ---------------- scratch (device globals; allocation is forbidden) ----------------
__device__ __half g_z[(size_t)M_ROWS * C_DIM];     // z = alpha @ x  (fp16, 201 MB)
__device__ __half g_wh[C_DIM * C_DIM];             // W in fp16, [k][n]
__device__ float  g_wa_l[C_DIM];                   // W @ a_l
__device__ float  g_wa_r[C_DIM];                   // W @ a_r

// ADJ_BASE rows as bitmasks (bit j set <=> ADJ_BASE[i][j] == 1)
__constant__ unsigned c_adj_row[12] = {
    0xFE8u, 0xFE8u, 0xFE8u, 0xFF7u, 0xFE8u, 0x1DFu,
    0xE3Fu, 0xE3Fu, 0xE3Fu, 0x1DFu, 0x1DFu, 0x1DFu
};

__device__ __forceinline__ uint32_t smem_u32(const void* p) {
    return (uint32_t)__cvta_generic_to_shared(p);
}

// ---------------- kernel 0a: W -> fp16 ----------------
__global__ void prep_w_kernel(const float* __restrict__ W) {
    int i = blockIdx.x * 512 + threadIdx.x;
    g_wh[i] = __float2half(W[i]);
}

// ---------------- kernel 0b: wa_l = W @ a_l, wa_r = W @ a_r (warp per k) ----------------
__global__ void prep_wa_kernel(const float* __restrict__ W,
                               const float* __restrict__ a_l,
                               const float* __restrict__ a_r) {
    int k = blockIdx.x * 8 + (threadIdx.x >> 5);   // 64 blocks * 8 warps = 512
    int lid = threadIdx.x & 31;
    const float* wr = W + (size_t)k * 512;
    float sl = 0.f, sr = 0.f;
    #pragma unroll
    for (int j = 0; j < 16; j++) {
        int n = lid + j * 32;
        float wv = wr[n];
        sl += wv * __ldg(a_l + n);
        sr += wv * __ldg(a_r + n);
    }
    #pragma unroll
    for (int o = 16; o; o >>= 1) {
        sl += __shfl_xor_sync(0xFFFFFFFFu, sl, o);
        sr += __shfl_xor_sync(0xFFFFFFFFu, sr, o);
    }
    if (lid == 0) { g_wa_l[k] = sl; g_wa_r[k] = sr; }
}

// ---------------- kernel 1: attention -> z = alpha @ x (fp16); 2 batches/block ----------------
__global__ void __launch_bounds__(256) attn_kernel(const float* __restrict__ x,
                                                   const float* __restrict__ adj_mask) {
    __shared__ float x_s[24 * 512];           // 48 KB: 2 batches
    __shared__ float s_el[24], s_er[24];
    __shared__ float alpha_s[24][12];
    const int b0 = blockIdx.x * 2;
    const int tid = threadIdx.x;
    const int wid = tid >> 5;
    const int lid = tid & 31;

    // load x for 2 batches (12288 floats = 3072 float4)
    const float4* xsrc = (const float4*)(x + (size_t)b0 * 6144);
    float4* xdst = (float4*)x_s;
    #pragma unroll
    for (int it = 0; it < 12; it++) xdst[tid + it * 256] = xsrc[tid + it * 256];
    __syncthreads();

    // el/er for 24 rows: warp w handles rows w, w+8, w+16
    #pragma unroll
    for (int rr = 0; rr < 3; rr++) {
        int row = wid + rr * 8;
        const float* xr = x_s + row * 512;
        float sl = 0.f, sr = 0.f;
        #pragma unroll
        for (int j = 0; j < 16; j++) {
            int d = lid + j * 32;
            float xv = xr[d];
            sl += xv * g_wa_l[d];
            sr += xv * g_wa_r[d];
        }
        #pragma unroll
        for (int o = 16; o; o >>= 1) {
            sl += __shfl_xor_sync(0xFFFFFFFFu, sl, o);
            sr += __shfl_xor_sync(0xFFFFFFFFu, sr, o);
        }
        if (lid == 0) { s_el[row] = sl; s_er[row] = sr; }
    }
    __syncthreads();

    // masked softmax: threads 0..23 (one per output node across 2 batches)
    if (tid < 24) {
        const int lb = tid / 12;              // local batch
        const int i  = tid - lb * 12;
        const unsigned rm = c_adj_row[i];
        const float eli = s_el[lb * 12 + i];
        const float* am = adj_mask + (size_t)(b0 + lb) * 144 + i * 12;
        float ev[12];
        bool keep[12];
        float mx = -3.4e38f;
        #pragma unroll
        for (int j = 0; j < 12; j++) {
            keep[j] = (j == i) || ((((rm >> j) & 1u) != 0u) && (am[j] > 0.1f));
            float v = eli + s_er[lb * 12 + j];
            v = (v > 0.f) ? v : 0.2f * v;     // leaky_relu(0.2)
            ev[j] = v;
            if (keep[j] && v > mx) mx = v;
        }
        float s = 0.f;
        #pragma unroll
        for (int j = 0; j < 12; j++) {
            float v = keep[j] ? expf(ev[j] - mx) : 0.f;
            alpha_s[tid][j] = v;
            s += v;
        }
        float inv = 1.f / s;
        #pragma unroll
        for (int j = 0; j < 12; j++) alpha_s[tid][j] *= inv;
    }
    __syncthreads();

    // z = alpha @ x: threads 0..127 -> batch 0, 128..255 -> batch 1
    const int t2 = tid & 127;
    const int lb = tid >> 7;
    float4 acc[12];
    #pragma unroll
    for (int n = 0; n < 12; n++) acc[n] = make_float4(0.f, 0.f, 0.f, 0.f);
    const float4* xs4 = (const float4*)x_s;
    #pragma unroll
    for (int m = 0; m < 12; m++) {
        float4 xv = xs4[(lb * 12 + m) * 128 + t2];
        #pragma unroll
        for (int n = 0; n < 12; n++) {
            float a = alpha_s[lb * 12 + n][m];
            acc[n].x += a * xv.x;
            acc[n].y += a * xv.y;
            acc[n].z += a * xv.z;
            acc[n].w += a * xv.w;
        }
    }
    #pragma unroll
    for (int n = 0; n < 12; n++) {
        __half2 p0 = __floats2half2_rn(acc[n].x, acc[n].y);
        __half2 p1 = __floats2half2_rn(acc[n].z, acc[n].w);
        uint2 u;
        u.x = *reinterpret_cast<uint32_t*>(&p0);
        u.y = *reinterpret_cast<uint32_t*>(&p1);
        *reinterpret_cast<uint2*>(g_z + (size_t)((b0 + lb) * 12 + n) * 512 + t2 * 4) = u;
    }
}

// ---------------- kernel 2: out = z @ W + x  (mma.sync fp16, fp32 accum) ----------------
// CTA tile 128(M) x 128(N), k-chunks of 64, 3-stage cp.async pipeline,
// ONE __syncthreads per chunk. 8 warps as 4(M) x 2(N); warp tile 32x64:
// 2 m-tiles x 8 n-tiles x 4 k-steps of m16n8k16 -> 64 MMA per chunk per warp.
#define A_STRIDE_B  144u     // bytes per A smem row (64 halves + 8 pad); 144%128=16 -> conflict-free
#define B_STRIDE_B  272u     // bytes per B smem row (128 halves + 8 pad); 272%128=16
#define A_STAGE_B   (128u * A_STRIDE_B)   // 18432
#define B_STAGE_B   (64u  * B_STRIDE_B)   // 17408
#define N_STAGE     3
#define GEMM_SMEM   (N_STAGE * (A_STAGE_B + B_STAGE_B))   // 107520 -> 2 CTAs = 215040 B/SM

__global__ void __launch_bounds__(256, 2) gemm_kernel(const float* __restrict__ x,
                                                      float* __restrict__ out) {
    extern __shared__ __align__(16) char smem[];

    const int tid = threadIdx.x;
    const int wid = tid >> 5;
    const int lid = tid & 31;
    const int warp_m = wid & 3;
    const int warp_n = wid >> 2;
    const int m0 = blockIdx.y * 128;
    const int n0 = blockIdx.x * 128;

    const uint32_t sA = smem_u32(smem);
    const uint32_t sB = sA + N_STAGE * A_STAGE_B;

    // ---- cp.async dst/src: A = 128 rows x 64 halves (1024 16B chunks, 4/thread) ----
    uint32_t adst[4];
    const __half* asrc[4];
    #pragma unroll
    for (int i = 0; i < 4; i++) {
        int c = tid + i * 256;
        adst[i] = (uint32_t)((c >> 3) * A_STRIDE_B + (c & 7) * 16);
        asrc[i] = g_z + (size_t)(m0 + (c >> 3)) * 512 + (c & 7) * 8;
    }
    // B = 64 rows x 128 halves (1024 16B chunks, 4/thread)
    uint32_t bdst[4];
    const __half* bsrc[4];
    #pragma unroll
    for (int i = 0; i < 4; i++) {
        int c = tid + i * 256;
        bdst[i] = (uint32_t)((c >> 4) * B_STRIDE_B + (c & 15) * 16);
        bsrc[i] = g_wh + (size_t)(c >> 4) * 512 + n0 + (c & 15) * 8;
    }

    // ldmatrix per-lane bases (warp covers 64 N-columns = 128 bytes)
    const int lm_row = ((lid >> 3) & 1) * 8 + (lid & 7);
    const int lm_col = (lid >> 4) * 16;             // bytes
    const uint32_t a_lm = sA + (uint32_t)((warp_m * 32 + lm_row) * A_STRIDE_B + lm_col);
    const uint32_t b_lm = sB + (uint32_t)(lm_row * B_STRIDE_B + warp_n * 128 + lm_col);

    float c[2][8][4];
    #pragma unroll
    for (int mt = 0; mt < 2; mt++)
        #pragma unroll
        for (int nt = 0; nt < 8; nt++)
            #pragma unroll
            for (int e = 0; e < 4; e++) c[mt][nt][e] = 0.f;

    // ---- prologue: issue chunks 0, 1 ----
    #pragma unroll
    for (int s = 0; s < N_STAGE - 1; s++) {
        const uint32_t ab = sA + s * A_STAGE_B;
        const uint32_t bb = sB + s * B_STAGE_B;
        #pragma unroll
        for (int i = 0; i < 4; i++)
            asm volatile("cp.async.cg.shared.global [%0], [%1], 16;"
                         :: "r"(ab + adst[i]), "l"(asrc[i] + s * 64));
        #pragma unroll
        for (int i = 0; i < 4; i++)
            asm volatile("cp.async.cg.shared.global [%0], [%1], 16;"
                         :: "r"(bb + bdst[i]), "l"(bsrc[i] + (size_t)s * 64 * 512));
        asm volatile("cp.async.commit_group;");
    }

    int cstage = 0, pstage = N_STAGE - 1;
    #pragma unroll 1
    for (int kc = 0; kc < 8; kc++) {
        asm volatile("cp.async.wait_group %0;" :: "n"(N_STAGE - 2));
        __syncthreads();

        // issue chunk kc+2 into buf pstage (held chunk kc-1: all warps done with it)
        if (kc + N_STAGE - 1 < 8) {
            const int s = kc + N_STAGE - 1;
            const uint32_t ab = sA + pstage * A_STAGE_B;
            const uint32_t bb = sB + pstage * B_STAGE_B;
            #pragma unroll
            for (int i = 0; i < 4; i++)
                asm volatile("cp.async.cg.shared.global [%0], [%1], 16;"
                             :: "r"(ab + adst[i]), "l"(asrc[i] + s * 64));
            #pragma unroll
            for (int i = 0; i < 4; i++)
                asm volatile("cp.async.cg.shared.global [%0], [%1], 16;"
                             :: "r"(bb + bdst[i]), "l"(bsrc[i] + (size_t)s * 64 * 512));
        }
        asm volatile("cp.async.commit_group;");

        const uint32_t abuf = a_lm + cstage * A_STAGE_B;
        const uint32_t bbuf = b_lm + cstage * B_STAGE_B;
        #pragma unroll
        for (int ks = 0; ks < 4; ks++) {
            uint32_t a[2][4], bf[8][2];
            #pragma unroll
            for (int mt = 0; mt < 2; mt++) {
                asm volatile("ldmatrix.sync.aligned.m8n8.x4.shared.b16 {%0,%1,%2,%3}, [%4];"
                             : "=r"(a[mt][0]), "=r"(a[mt][1]), "=r"(a[mt][2]), "=r"(a[mt][3])
                             : "r"(abuf + (uint32_t)(mt * 16 * A_STRIDE_B + ks * 32)));
            }
            #pragma unroll
            for (int i = 0; i < 4; i++) {
                asm volatile("ldmatrix.sync.aligned.m8n8.x4.trans.shared.b16 {%0,%1,%2,%3}, [%4];"
                             : "=r"(bf[2*i][0]), "=r"(bf[2*i][1]),
                               "=r"(bf[2*i+1][0]), "=r"(bf[2*i+1][1])
                             : "r"(bbuf + (uint32_t)(ks * 16 * B_STRIDE_B + i * 32)));
            }
            #pragma unroll
            for (int mt = 0; mt < 2; mt++)
                #pragma unroll
                for (int nt = 0; nt < 8; nt++) {
                    asm volatile(
                        "mma.sync.aligned.m16n8k16.row.col.f32.f16.f16.f32 "
                        "{%0,%1,%2,%3}, {%4,%5,%6,%7}, {%8,%9}, {%0,%1,%2,%3};"
                        : "+f"(c[mt][nt][0]), "+f"(c[mt][nt][1]),
                          "+f"(c[mt][nt][2]), "+f"(c[mt][nt][3])
                        : "r"(a[mt][0]), "r"(a[mt][1]), "r"(a[mt][2]), "r"(a[mt][3]),
                          "r"(bf[nt][0]), "r"(bf[nt][1]));
                }
        }
        cstage = (cstage + 1 == N_STAGE) ? 0 : cstage + 1;
        pstage = (pstage + 1 == N_STAGE) ? 0 : pstage + 1;
    }

    // ---- epilogue: out = c + x (warp covers 64 N-cols: base warp_n*64) ----
    const int rbase = m0 + warp_m * 32 + (lid >> 2);
    const int cbase = n0 + warp_n * 64 + (lid & 3) * 2;
    #pragma unroll
    for (int mt = 0; mt < 2; mt++) {
        #pragma unroll
        for (int nt = 0; nt < 8; nt++) {
            int col = cbase + nt * 8;
            {
                size_t o = (size_t)(rbase + mt * 16) * 512 + col;
                float2 xv = *reinterpret_cast<const float2*>(x + o);
                float2 r = make_float2(c[mt][nt][0] + xv.x, c[mt][nt][1] + xv.y);
                *reinterpret_cast<float2*>(out + o) = r;
            }
            {
                size_t o = (size_t)(rbase + mt * 16 + 8) * 512 + col;
                float2 xv = *reinterpret_cast<const float2*>(x + o);
                float2 r = make_float2(c[mt][nt][2] + xv.x, c[mt][nt][3] + xv.y);
                *reinterpret_cast<float2*>(out + o) = r;
            }
        }
    }
}

// ---------------- launch ----------------
extern "C" void kernel_launch(void* const* d_in, const int* in_sizes, int n_in,
                              void* d_out, int out_size) {
    const float* x        = (const float*)d_in[0];
    const float* adj_mask = (const float*)d_in[1];
    const float* W        = (const float*)d_in[2];
    const float* a_l      = (const float*)d_in[3];
    const float* a_r      = (const float*)d_in[4];
    float* out = (float*)d_out;

    cudaFuncSetAttribute(gemm_kernel, cudaFuncAttributeMaxDynamicSharedMemorySize, GEMM_SMEM);

    prep_w_kernel<<<512, 512>>>(W);
    prep_wa_kernel<<<64, 256>>>(W, a_l, a_r);
    attn_kernel<<<B_SZ / 2, 256>>>(x, adj_mask);
    gemm_kernel<<<dim3(4, 1536), 256, GEMM_SMEM>>>(x, out);
}

// round 11
// speedup vs baseline: 1.0511x; 1.0511x over previous
#include <cuda_runtime.h>
#include <cuda_fp16.h>
#include <stdint.h>

#define B_SZ   16384
#define N_NODE 12
#define C_DIM  512
#define M_ROWS (B_SZ * N_NODE)   // 196608

// ---------------- scratch (device globals; allocation is forbidden) ----------------
__device__ __half g_z[(size_t)M_ROWS * C_DIM];     // z = alpha @ x  (fp16, 201 MB)
__device__ __half g_wh[C_DIM * C_DIM];             // W in fp16, [k][n]
__device__ float  g_wa_l[C_DIM];                   // W @ a_l
__device__ float  g_wa_r[C_DIM];                   // W @ a_r

// ADJ_BASE rows as bitmasks (bit j set <=> ADJ_BASE[i][j] == 1)
__constant__ unsigned c_adj_row[12] = {
    0xFE8u, 0xFE8u, 0xFE8u, 0xFF7u, 0xFE8u, 0x1DFu,
    0xE3Fu, 0xE3Fu, 0xE3Fu, 0x1DFu, 0x1DFu, 0x1DFu
};

__device__ __forceinline__ uint32_t smem_u32(const void* p) {
    return (uint32_t)__cvta_generic_to_shared(p);
}

// ---------------- kernel 0a: W -> fp16 ----------------
__global__ void prep_w_kernel(const float* __restrict__ W) {
    int i = blockIdx.x * 512 + threadIdx.x;
    g_wh[i] = __float2half(W[i]);
}

// ---------------- kernel 0b: wa_l = W @ a_l, wa_r = W @ a_r (warp per k) ----------------
__global__ void prep_wa_kernel(const float* __restrict__ W,
                               const float* __restrict__ a_l,
                               const float* __restrict__ a_r) {
    int k = blockIdx.x * 8 + (threadIdx.x >> 5);   // 64 blocks * 8 warps = 512
    int lid = threadIdx.x & 31;
    const float* wr = W + (size_t)k * 512;
    float sl = 0.f, sr = 0.f;
    #pragma unroll
    for (int j = 0; j < 16; j++) {
        int n = lid + j * 32;
        float wv = wr[n];
        sl += wv * __ldg(a_l + n);
        sr += wv * __ldg(a_r + n);
    }
    #pragma unroll
    for (int o = 16; o; o >>= 1) {
        sl += __shfl_xor_sync(0xFFFFFFFFu, sl, o);
        sr += __shfl_xor_sync(0xFFFFFFFFu, sr, o);
    }
    if (lid == 0) { g_wa_l[k] = sl; g_wa_r[k] = sr; }
}

// ---------------- kernel 1: attention -> z = alpha @ x (fp16) ----------------
// Register-resident: thread t holds x[m][4t..4t+3] for all 12 m. No x smem.
__global__ void __launch_bounds__(128, 4) attn_kernel(const float* __restrict__ x,
                                                      const float* __restrict__ adj_mask) {
    __shared__ float red[4][24];        // per-warp el/er partials
    __shared__ float s_el[12], s_er[12];
    __shared__ float alpha_s[12][12];
    const int b = blockIdx.x;
    const int tid = threadIdx.x;
    const int wid = tid >> 5;
    const int lid = tid & 31;

    // x tile in registers: 12 float4 per thread (coalesced: thread t -> cols 4t..4t+3)
    float4 xr[12];
    const float4* xs = (const float4*)(x + (size_t)b * 6144);
    #pragma unroll
    for (int m = 0; m < 12; m++) xr[m] = xs[m * 128 + tid];

    // per-thread el/er partials over 4 owned columns
    const float4 wl = *reinterpret_cast<const float4*>(g_wa_l + tid * 4);
    const float4 wr = *reinterpret_cast<const float4*>(g_wa_r + tid * 4);
    float pel[12], per[12];
    #pragma unroll
    for (int m = 0; m < 12; m++) {
        pel[m] = xr[m].x * wl.x + xr[m].y * wl.y + xr[m].z * wl.z + xr[m].w * wl.w;
        per[m] = xr[m].x * wr.x + xr[m].y * wr.y + xr[m].z * wr.z + xr[m].w * wr.w;
    }
    // warp reduction
    #pragma unroll
    for (int o = 16; o; o >>= 1) {
        #pragma unroll
        for (int m = 0; m < 12; m++) {
            pel[m] += __shfl_xor_sync(0xFFFFFFFFu, pel[m], o);
            per[m] += __shfl_xor_sync(0xFFFFFFFFu, per[m], o);
        }
    }
    if (lid == 0) {
        #pragma unroll
        for (int m = 0; m < 12; m++) {
            red[wid][m] = pel[m];
            red[wid][12 + m] = per[m];
        }
    }
    __syncthreads();

    // warp 0: finish reduction + masked softmax
    if (tid < 32) {
        if (tid < 24) {
            float v = red[0][tid] + red[1][tid] + red[2][tid] + red[3][tid];
            if (tid < 12) s_el[tid] = v; else s_er[tid - 12] = v;
        }
        __syncwarp();
        if (tid < 12) {
            const int i = tid;
            const unsigned rm = c_adj_row[i];
            const float eli = s_el[i];
            const float* am = adj_mask + (size_t)b * 144 + i * 12;
            float ev[12];
            bool keep[12];
            float mx = -3.4e38f;
            #pragma unroll
            for (int j = 0; j < 12; j++) {
                keep[j] = (j == i) || ((((rm >> j) & 1u) != 0u) && (am[j] > 0.1f));
                float v = eli + s_er[j];
                v = (v > 0.f) ? v : 0.2f * v;   // leaky_relu(0.2)
                ev[j] = v;
                if (keep[j] && v > mx) mx = v;
            }
            float s = 0.f;
            #pragma unroll
            for (int j = 0; j < 12; j++) {
                float v = keep[j] ? expf(ev[j] - mx) : 0.f;
                alpha_s[i][j] = v;
                s += v;
            }
            float inv = 1.f / s;
            #pragma unroll
            for (int j = 0; j < 12; j++) alpha_s[i][j] *= inv;
        }
    }
    __syncthreads();

    // z = alpha @ x from registers; broadcast alpha from smem
    float4 acc[12];
    #pragma unroll
    for (int n = 0; n < 12; n++) acc[n] = make_float4(0.f, 0.f, 0.f, 0.f);
    #pragma unroll
    for (int m = 0; m < 12; m++) {
        float4 xv = xr[m];
        #pragma unroll
        for (int n = 0; n < 12; n++) {
            float a = alpha_s[n][m];
            acc[n].x += a * xv.x;
            acc[n].y += a * xv.y;
            acc[n].z += a * xv.z;
            acc[n].w += a * xv.w;
        }
    }
    #pragma unroll
    for (int n = 0; n < 12; n++) {
        __half2 p0 = __floats2half2_rn(acc[n].x, acc[n].y);
        __half2 p1 = __floats2half2_rn(acc[n].z, acc[n].w);
        uint2 u;
        u.x = *reinterpret_cast<uint32_t*>(&p0);
        u.y = *reinterpret_cast<uint32_t*>(&p1);
        *reinterpret_cast<uint2*>(g_z + (size_t)(b * 12 + n) * 512 + tid * 4) = u;
    }
}

// ---------------- kernel 2: out = z @ W + x  (mma.sync fp16, fp32 accum) ----------------
// R9 config (measured 383.7us ~= mma.sync ceiling): CTA tile 128x128, k-chunks of 32,
// 3-stage cp.async, one __syncthreads per chunk. 8 warps as 4(M) x 2(N); warp tile 32x64.
#define A_STRIDE_B  80u      // bytes per A smem row (32 halves + 8 pad)
#define B_STRIDE_B  272u     // bytes per B smem row (128 halves + 8 pad)
#define A_STAGE_B   (128u * A_STRIDE_B)   // 10240
#define B_STAGE_B   (32u  * B_STRIDE_B)   // 8704
#define N_STAGE     3
#define GEMM_SMEM   (N_STAGE * (A_STAGE_B + B_STAGE_B))   // 56832

__global__ void __launch_bounds__(256, 2) gemm_kernel(const float* __restrict__ x,
                                                      float* __restrict__ out) {
    extern __shared__ __align__(16) char smem[];

    const int tid = threadIdx.x;
    const int wid = tid >> 5;
    const int lid = tid & 31;
    const int warp_m = wid & 3;
    const int warp_n = wid >> 2;
    const int m0 = blockIdx.y * 128;
    const int n0 = blockIdx.x * 128;

    const uint32_t sA = smem_u32(smem);
    const uint32_t sB = sA + N_STAGE * A_STAGE_B;

    // A: 128 rows x 32 cols x 2B = 512 chunks of 16B; 2 per thread.
    const int ac0 = tid, ac1 = tid + 256;
    const uint32_t adst0 = (uint32_t)((ac0 >> 2) * A_STRIDE_B + (ac0 & 3) * 16);
    const uint32_t adst1 = (uint32_t)((ac1 >> 2) * A_STRIDE_B + (ac1 & 3) * 16);
    const __half* asrc0 = g_z + (size_t)(m0 + (ac0 >> 2)) * 512 + (ac0 & 3) * 8;
    const __half* asrc1 = g_z + (size_t)(m0 + (ac1 >> 2)) * 512 + (ac1 & 3) * 8;
    // B: 32 rows x 128 cols x 2B = 512 chunks of 16B; 2 per thread.
    const int bc0 = tid, bc1 = tid + 256;
    const uint32_t bdst0 = (uint32_t)((bc0 >> 4) * B_STRIDE_B + (bc0 & 15) * 16);
    const uint32_t bdst1 = (uint32_t)((bc1 >> 4) * B_STRIDE_B + (bc1 & 15) * 16);
    const __half* bsrc0 = g_wh + (size_t)(bc0 >> 4) * 512 + n0 + (bc0 & 15) * 8;
    const __half* bsrc1 = g_wh + (size_t)(bc1 >> 4) * 512 + n0 + (bc1 & 15) * 8;

    // ldmatrix per-lane bases (warp covers 64 N-columns = 128 bytes)
    const int lm_row = ((lid >> 3) & 1) * 8 + (lid & 7);
    const int lm_col = (lid >> 4) * 16;             // bytes
    const uint32_t a_lm = sA + (uint32_t)((warp_m * 32 + lm_row) * A_STRIDE_B + lm_col);
    const uint32_t b_lm = sB + (uint32_t)(lm_row * B_STRIDE_B + warp_n * 128 + lm_col);

    float c[2][8][4];
    #pragma unroll
    for (int mt = 0; mt < 2; mt++)
        #pragma unroll
        for (int nt = 0; nt < 8; nt++)
            #pragma unroll
            for (int e = 0; e < 4; e++) c[mt][nt][e] = 0.f;

    // prologue: issue stages 0, 1
    #pragma unroll
    for (int s = 0; s < N_STAGE - 1; s++) {
        const uint32_t ab = sA + s * A_STAGE_B;
        const uint32_t bb = sB + s * B_STAGE_B;
        asm volatile("cp.async.cg.shared.global [%0], [%1], 16;" :: "r"(ab + adst0), "l"(asrc0 + s * 32));
        asm volatile("cp.async.cg.shared.global [%0], [%1], 16;" :: "r"(ab + adst1), "l"(asrc1 + s * 32));
        asm volatile("cp.async.cg.shared.global [%0], [%1], 16;" :: "r"(bb + bdst0), "l"(bsrc0 + (size_t)s * 32 * 512));
        asm volatile("cp.async.cg.shared.global [%0], [%1], 16;" :: "r"(bb + bdst1), "l"(bsrc1 + (size_t)s * 32 * 512));
        asm volatile("cp.async.commit_group;");
    }

    int cstage = 0, pstage = N_STAGE - 1;
    #pragma unroll 1
    for (int kc = 0; kc < 16; kc++) {
        asm volatile("cp.async.wait_group %0;" :: "n"(N_STAGE - 2));
        __syncthreads();

        if (kc + N_STAGE - 1 < 16) {
            const int s = kc + N_STAGE - 1;
            const uint32_t ab = sA + pstage * A_STAGE_B;
            const uint32_t bb = sB + pstage * B_STAGE_B;
            asm volatile("cp.async.cg.shared.global [%0], [%1], 16;" :: "r"(ab + adst0), "l"(asrc0 + s * 32));
            asm volatile("cp.async.cg.shared.global [%0], [%1], 16;" :: "r"(ab + adst1), "l"(asrc1 + s * 32));
            asm volatile("cp.async.cg.shared.global [%0], [%1], 16;" :: "r"(bb + bdst0), "l"(bsrc0 + (size_t)s * 32 * 512));
            asm volatile("cp.async.cg.shared.global [%0], [%1], 16;" :: "r"(bb + bdst1), "l"(bsrc1 + (size_t)s * 32 * 512));
        }
        asm volatile("cp.async.commit_group;");

        const uint32_t abuf = a_lm + cstage * A_STAGE_B;
        const uint32_t bbuf = b_lm + cstage * B_STAGE_B;
        #pragma unroll
        for (int ks = 0; ks < 2; ks++) {
            uint32_t a[2][4], bf[8][2];
            #pragma unroll
            for (int mt = 0; mt < 2; mt++) {
                asm volatile("ldmatrix.sync.aligned.m8n8.x4.shared.b16 {%0,%1,%2,%3}, [%4];"
                             : "=r"(a[mt][0]), "=r"(a[mt][1]), "=r"(a[mt][2]), "=r"(a[mt][3])
                             : "r"(abuf + (uint32_t)(mt * 16 * A_STRIDE_B + ks * 32)));
            }
            #pragma unroll
            for (int i = 0; i < 4; i++) {
                asm volatile("ldmatrix.sync.aligned.m8n8.x4.trans.shared.b16 {%0,%1,%2,%3}, [%4];"
                             : "=r"(bf[2*i][0]), "=r"(bf[2*i][1]),
                               "=r"(bf[2*i+1][0]), "=r"(bf[2*i+1][1])
                             : "r"(bbuf + (uint32_t)(ks * 16 * B_STRIDE_B + i * 32)));
            }
            #pragma unroll
            for (int mt = 0; mt < 2; mt++)
                #pragma unroll
                for (int nt = 0; nt < 8; nt++) {
                    asm volatile(
                        "mma.sync.aligned.m16n8k16.row.col.f32.f16.f16.f32 "
                        "{%0,%1,%2,%3}, {%4,%5,%6,%7}, {%8,%9}, {%0,%1,%2,%3};"
                        : "+f"(c[mt][nt][0]), "+f"(c[mt][nt][1]),
                          "+f"(c[mt][nt][2]), "+f"(c[mt][nt][3])
                        : "r"(a[mt][0]), "r"(a[mt][1]), "r"(a[mt][2]), "r"(a[mt][3]),
                          "r"(bf[nt][0]), "r"(bf[nt][1]));
                }
        }
        cstage = (cstage + 1 == N_STAGE) ? 0 : cstage + 1;
        pstage = (pstage + 1 == N_STAGE) ? 0 : pstage + 1;
    }

    // epilogue: out = c + x (warp covers 64 N-cols: base warp_n*64)
    const int rbase = m0 + warp_m * 32 + (lid >> 2);
    const int cbase = n0 + warp_n * 64 + (lid & 3) * 2;
    #pragma unroll
    for (int mt = 0; mt < 2; mt++) {
        #pragma unroll
        for (int nt = 0; nt < 8; nt++) {
            int col = cbase + nt * 8;
            {
                size_t o = (size_t)(rbase + mt * 16) * 512 + col;
                float2 xv = *reinterpret_cast<const float2*>(x + o);
                float2 r = make_float2(c[mt][nt][0] + xv.x, c[mt][nt][1] + xv.y);
                *reinterpret_cast<float2*>(out + o) = r;
            }
            {
                size_t o = (size_t)(rbase + mt * 16 + 8) * 512 + col;
                float2 xv = *reinterpret_cast<const float2*>(x + o);
                float2 r = make_float2(c[mt][nt][2] + xv.x, c[mt][nt][3] + xv.y);
                *reinterpret_cast<float2*>(out + o) = r;
            }
        }
    }
}

// ---------------- launch ----------------
extern "C" void kernel_launch(void* const* d_in, const int* in_sizes, int n_in,
                              void* d_out, int out_size) {
    const float* x        = (const float*)d_in[0];
    const float* adj_mask = (const float*)d_in[1];
    const float* W        = (const float*)d_in[2];
    const float* a_l      = (const float*)d_in[3];
    const float* a_r      = (const float*)d_in[4];
    float* out = (float*)d_out;

    cudaFuncSetAttribute(gemm_kernel, cudaFuncAttributeMaxDynamicSharedMemorySize, GEMM_SMEM);

    prep_w_kernel<<<512, 512>>>(W);
    prep_wa_kernel<<<64, 256>>>(W, a_l, a_r);
    attn_kernel<<<B_SZ, 128>>>(x, adj_mask);
    gemm_kernel<<<dim3(4, 1536), 256, GEMM_SMEM>>>(x, out);
}